// round 17
// baseline (speedup 1.0000x reference)
#include <cuda_runtime.h>
#include <cstdint>

// DispCorrM via banded tf32 mma.sync (HMMA) GEMM.
// R17: R11 skeleton, but the warp's two m16-tiles are computed SEQUENTIALLY
// (outer half loop, inner ks loop) so only 40 C-floats are live at once.
// True live set ~80 regs -> 5 CTAs/SM without ptxas spills (R16's failure).
// K-split cp.async overlap preserved for half 0; half 1 extends the compute
// span that overlaps other CTAs' loads (the mechanism driving DRAM util).
//
// out[b,d,h,w] = (1/32) * sum_c L[c,w] * R[c,w-d]   (0 if w<d)
// Per CTA (b, h, w-tile of 128): D[m,n] = sum_c A[c][m]*B[c][n]
//   A[c][m] = L[c, w0+m]      (smem rows of 128, stride 136: 8t+g banks)
//   B[c][n] = R[c, w0-64+n]   (smem rows of 192, stride 200, halo zero-filled)
//   out[d, w0+m] = D[m, m+64-d]/32
// Band: per m16-tile mt only n in [16mt, 16mt+80) needed (10 n8-tiles).

#define BB    4
#define CCH   32
#define HH    256
#define WW    512
#define DDISP 64
#define HW    ((size_t)HH * WW)

#define SA   136    // A row stride (floats); mod 32 = 8 -> conflict-free frags
#define SB   200    // B row stride (floats); mod 32 = 8
#define OPAD 132    // staging row stride (floats); conflict-free band STS

__device__ __forceinline__ uint32_t f2tf32(float v) {
    uint32_t t;
    asm("cvt.rna.tf32.f32 %0, %1;" : "=r"(t) : "f"(v));
    return t;
}
__device__ __forceinline__ void cp16(uint32_t sa, const void* g, uint32_t src_bytes) {
    asm volatile("cp.async.cg.shared.global [%0], [%1], 16, %2;"
                 :: "r"(sa), "l"(g), "r"(src_bytes));
}
__device__ __forceinline__ void mma8(float* c, const uint32_t* a, uint32_t b0, uint32_t b1) {
    asm volatile(
        "mma.sync.aligned.m16n8k8.row.col.f32.tf32.tf32.f32 "
        "{%0,%1,%2,%3}, {%4,%5,%6,%7}, {%8,%9}, {%0,%1,%2,%3};"
        : "+f"(c[0]), "+f"(c[1]), "+f"(c[2]), "+f"(c[3])
        : "r"(a[0]), "r"(a[1]), "r"(a[2]), "r"(a[3]), "r"(b0), "r"(b1));
}

__global__ __launch_bounds__(128, 5)
void disp_corr_mma_kernel(const float* __restrict__ x, float* __restrict__ out) {
    __shared__ union {
        struct {
            float A[CCH * SA];       // 17.4 KB, raw fp32 L rows
            float B[CCH * SB];       // 25.6 KB, raw fp32 R rows
        } in;
        float O[DDISP * OPAD];       // 33.8 KB staging (aliased after mainloop)
    } sm;

    const int tid  = threadIdx.x;
    const int lane = tid & 31;
    const int warp = tid >> 5;          // 0..3
    const int g    = lane >> 2;         // 0..7
    const int t    = lane & 3;          // 0..3
    const int tile = blockIdx.x;        // 0..3
    const int h    = blockIdx.y;
    const int b    = blockIdx.z;
    const int w0   = tile * 128;

    const float* Lg = x + (((size_t)b * 2 * CCH) * HH + h) * WW + w0;
    const float* Rg = x + (((size_t)b * 2 * CCH + CCH) * HH + h) * WW;

    const uint32_t abase = (uint32_t)__cvta_generic_to_shared(sm.in.A);
    const uint32_t bbase = (uint32_t)__cvta_generic_to_shared(sm.in.B);

    // ---- K-chunk loader: channels [c0, c0+16). A: 512 granules, B: 768. ----
    auto load_half_k = [&](int c0) {
        #pragma unroll
        for (int k = 0; k < 4; k++) {                 // A: 512 granules / 128 thr
            int idx = k * 128 + tid;
            int c = c0 + (idx >> 5), q = idx & 31;
            cp16(abase + (c * SA + 4 * q) * 4, Lg + (size_t)c * HW + 4 * q, 16);
        }
        #pragma unroll
        for (int k = 0; k < 6; k++) {                 // B: 768 granules / 128 thr
            int idx = k * 128 + tid;
            int c = c0 + idx / 48, q = idx % 48;
            int wg = w0 - 64 + 4 * q;                 // granule-aligned: all-in or all-out
            const float* src = Rg + (size_t)c * HW + (wg >= 0 ? wg : 0);
            cp16(bbase + (c * SB + 4 * q) * 4, src, wg >= 0 ? 16u : 0u);
        }
        asm volatile("cp.async.commit_group;");
    };

    load_half_k(0);    // group 0: channels 0-15  (ks 0,1)
    load_half_k(16);   // group 1: channels 16-31 (ks 2,3)

    asm volatile("cp.async.wait_group 1;");   // chunk 0 landed
    __syncthreads();

    const float* bp0 = &sm.in.B[t * SB + 32 * warp + g];
    const float inv_c = 1.0f / 32.0f;
    bool chunk1_done = false;

    // ---- Sequential m-tile halves: m16-tile = 2*warp + half ----
    #pragma unroll
    for (int half = 0; half < 2; half++) {
        const float* ap = &sm.in.A[t * SA + 32 * warp + 16 * half + g];
        const float* bp = bp0 + 16 * half;

        float C[10][4];
        #pragma unroll
        for (int j = 0; j < 10; j++)
            #pragma unroll
            for (int r = 0; r < 4; r++) C[j][r] = 0.f;

        #pragma unroll
        for (int ks = 0; ks < 4; ks++) {
            if (ks == 2 && !chunk1_done) {
                asm volatile("cp.async.wait_group 0;");   // chunk 1 landed
                __syncthreads();
                chunk1_done = true;
            }
            const float* a = ap + 8 * ks * SA;
            uint32_t af[4];
            af[0] = f2tf32(a[0]);           af[1] = f2tf32(a[8]);
            af[2] = f2tf32(a[4 * SA]);      af[3] = f2tf32(a[4 * SA + 8]);

            const float* bb = bp + 8 * ks * SB;
            #pragma unroll
            for (int j = 0; j < 10; j++) {
                uint32_t b0 = f2tf32(bb[8 * j]);
                uint32_t b1 = f2tf32(bb[4 * SB + 8 * j]);
                mma8(C[j], af, b0, b1);
            }
        }

        if (half == 1) __syncthreads();   // before aliasing smem as staging
        // half 0 writes into sm.O only AFTER... careful: sm.O aliases sm.in!
        // -> half 0 must stage to registers? No: half 0's staging writes would
        //    corrupt B rows still needed by half 1. Solution: write half 0's
        //    band into the output staging REGION that does not overlap B:
        //    impossible in general. Instead: half 0 stages nothing; both
        //    halves' extractions happen after the union flip. So C for half 0
        //    must persist... which defeats the register saving.
        // Resolution: extract half 0 into the NON-overlapping low part of O?
        // O rows d use O[d*OPAD + m]: half 0 writes columns m in
        // [32w, 32w+16) for all d -> scattered across the whole union. No.
        // => stage half 0 directly to GMEM (scalar STG.32, coalesced in
        //    32B sectors), half 1 likewise; drop the smem staging entirely.
        {
            const int mbase = 32 * warp + 16 * half + g;
            float* op = out + (((size_t)b * DDISP) * HH + h) * WW + w0;
            #pragma unroll
            for (int j = 0; j < 10; j++) {
                const int dbase = g + 64 - 8 * j - 2 * t;
                if ((unsigned)dbase       < 64u) op[(size_t)dbase       * HW + mbase]     = C[j][0] * inv_c;
                if ((unsigned)(dbase - 1) < 64u) op[(size_t)(dbase - 1) * HW + mbase]     = C[j][1] * inv_c;
                if ((unsigned)(dbase + 8) < 64u) op[(size_t)(dbase + 8) * HW + mbase + 8] = C[j][2] * inv_c;
                if ((unsigned)(dbase + 7) < 64u) op[(size_t)(dbase + 7) * HW + mbase + 8] = C[j][3] * inv_c;
            }
        }
    }
}

extern "C" void kernel_launch(void* const* d_in, const int* in_sizes, int n_in,
                              void* d_out, int out_size) {
    const float* x = (const float*)d_in[0];
    float* out = (float*)d_out;
    dim3 grid(WW / 128, HH, BB);   // (4, 256, 4) = 4096 blocks
    disp_corr_mma_kernel<<<grid, 128>>>(x, out);
}